// round 4
// baseline (speedup 1.0000x reference)
#include <cuda_runtime.h>

// SchrodingerOperator: H = tridiag(-1, 2, -1)/dx^2 + diag(V), N=8192, fp32 dense out.
// Pure store kernel: 256 MiB of mostly zeros + 3 diagonals.
// This version: one 256-bit store (st.global.v8.f32) per thread to halve the
// L1tex/LSU store-instruction pressure (L1 was at 70% alongside DRAM 69%).

#define NN 8192
#define NV8 (NN / 8)          // 1024 v8-chunks per row
#define N_MODES 12

__global__ void __launch_bounds__(256)
schrodinger_fill_v8_kernel(const float* __restrict__ a0,
                           const float* __restrict__ cos_coeff,
                           const float* __restrict__ sin_coeff,
                           float* __restrict__ out)
{
    // One 32-byte chunk of the matrix per thread. Grid exactly covers N*N/8.
    unsigned int idx = blockIdx.x * blockDim.x + threadIdx.x;   // 0 .. 8M-1
    int row  = (int)(idx >> 10);          // idx / 1024
    int c8   = (int)(idx & 1023u);        // idx % 1024
    int col0 = c8 << 3;                   // first column of this chunk

    float v0 = 0.f, v1 = 0.f, v2 = 0.f, v3 = 0.f;
    float v4 = 0.f, v5 = 0.f, v6 = 0.f, v7 = 0.f;

    // Tridiagonal band for this row spans columns [row-1, row+1].
    if (col0 + 7 >= row - 1 && col0 <= row + 1) {
        const float inv_dx2 = 67108864.0f;          // 8192^2
        // Compute V[row]
        const float x = (float)row * (1.0f / (float)(NN - 1));
        float Vr = a0[0];
        #pragma unroll
        for (int k = 0; k < N_MODES; k++) {
            float ph = 6.28318530717958647692f * (float)(k + 1) * x;
            float s, c;
            sincosf(ph, &s, &c);
            Vr = fmaf(cos_coeff[k], c, Vr);
            Vr = fmaf(sin_coeff[k], s, Vr);
        }
        const float diag_val = fmaf(2.0f, inv_dx2, Vr);
        const float off_val  = -inv_dx2;

        float vals[8];
        #pragma unroll
        for (int j = 0; j < 8; j++) {
            int col = col0 + j;
            float val = 0.f;
            if (col == row)                            val = diag_val;
            else if (col == row - 1 || col == row + 1) val = off_val;
            vals[j] = val;
        }
        v0 = vals[0]; v1 = vals[1]; v2 = vals[2]; v3 = vals[3];
        v4 = vals[4]; v5 = vals[5]; v6 = vals[6]; v7 = vals[7];
    }

    float* p = out + ((size_t)idx << 3);   // 32B-aligned (allocation-aligned base)
    asm volatile(
        "st.global.v8.f32 [%0], {%1, %2, %3, %4, %5, %6, %7, %8};"
        :: "l"(p),
           "f"(v0), "f"(v1), "f"(v2), "f"(v3),
           "f"(v4), "f"(v5), "f"(v6), "f"(v7)
        : "memory");
}

extern "C" void kernel_launch(void* const* d_in, const int* in_sizes, int n_in,
                              void* d_out, int out_size)
{
    const float* a0        = (const float*)d_in[0];
    const float* cos_coeff = (const float*)d_in[1];
    const float* sin_coeff = (const float*)d_in[2];
    float* out = (float*)d_out;

    // total v8 elements = 8192*8192/8 = 8,388,608
    const unsigned int total8 = (unsigned int)NN * (unsigned int)NV8;
    const int threads = 256;
    const unsigned int blocks = total8 / threads;   // 32768, exact

    schrodinger_fill_v8_kernel<<<blocks, threads>>>(a0, cos_coeff, sin_coeff, out);
}